// round 7
// baseline (speedup 1.0000x reference)
#include <cuda_runtime.h>
#include <cuda_bf16.h>
#include <cstdint>

// Problem constants (B=32, T=2048, D_IN=1024, H1=512, H2=32)
#define NB_   32
#define T_    2048
#define DIN   1024
#define H1_   512
#define ROWS  (NB_ * T_)   // 65536

// GEMM tiling: CTA = 128 x 256, 512 threads (16 warps as 4Mx4N, warp tile 32x64)
#define MTILE 128
#define NTILE 256
#define KC    64           // K per smem stage
#define NSTG  (DIN / KC)   // 16 stages

#define AS_STRIDE 72       // bf16 elems/row: 144B -> 8 rows hit distinct 16B chunks mod 128
#define BS_STRIDE 264      // bf16 elems/row: 528B -> conflict-free for ldmatrix.trans

// ---------------- device scratch ----------------
__device__ __nv_bfloat16 g_w1b[DIN * H1_];   // W1 bf16, row-major [k][n]
__device__ float         g_weff[H1_];        // W2 @ W3
__device__ float         g_beff;             // b2 . W3 + b3
__device__ float         g_z[ROWS];          // pre-sigmoid logits (minus beff)

// ---------------- kernel 0: prep ----------------
__global__ void prep_kernel(const float* __restrict__ W1,
                            const float* __restrict__ W2,
                            const float* __restrict__ b2,
                            const float* __restrict__ W3,
                            const float* __restrict__ b3) {
    int gid    = blockIdx.x * blockDim.x + threadIdx.x;
    int stride = gridDim.x * blockDim.x;
    for (int i = gid; i < DIN * H1_; i += stride)
        g_w1b[i] = __float2bfloat16(W1[i]);
    if (gid < H1_) {
        float s = 0.f;
        #pragma unroll
        for (int c = 0; c < 32; ++c) s += W2[gid * 32 + c] * W3[c];
        g_weff[gid] = s;
    }
    if (gid == 0) {
        float s = b3[0];
        #pragma unroll
        for (int c = 0; c < 32; ++c) s += b2[c] * W3[c];
        g_beff = s;
    }
}

// ---------------- kernel 1: fused GEMM + bias + relu + weff-dot ----------------
struct __align__(16) Smem {
    __nv_bfloat16 As[2][MTILE][AS_STRIDE];   // 36864 B
    __nv_bfloat16 Bs[2][KC][BS_STRIDE];      // 67584 B
    float b1s[NTILE];                        //  1024 B
    float wsm[NTILE];                        //  1024 B
    float zs[MTILE];                         //   512 B
};                                           // 107008 B total

__global__ __launch_bounds__(512, 1)
void mlp_gemm_kernel(const float* __restrict__ A, const float* __restrict__ b1) {
    extern __shared__ char smem_raw[];
    Smem& sm = *reinterpret_cast<Smem*>(smem_raw);

    const int tid  = threadIdx.x;
    const int lane = tid & 31;
    const int warp = tid >> 5;
    const int wm   = warp >> 2;   // 0..3  (M groups of 32 rows)
    const int wn   = warp & 3;    // 0..3  (N groups of 64 cols)

    const int nt_blk   = blockIdx.x & 1;     // which 256-col half of H1
    const int row_tile = blockIdx.x >> 1;    // 0..511
    const int row_base = row_tile * MTILE;
    const int n_base   = nt_blk * NTILE;

    // epilogue constants + zero row sums (covered by prologue __syncthreads)
    if (tid < NTILE) {
        sm.b1s[tid] = b1[n_base + tid];
        sm.wsm[tid] = g_weff[n_base + tid];
    }
    if (tid < MTILE) sm.zs[tid] = 0.f;

    float acc[2][8][4];
    #pragma unroll
    for (int a = 0; a < 2; ++a)
        #pragma unroll
        for (int b = 0; b < 8; ++b)
            #pragma unroll
            for (int c = 0; c < 4; ++c) acc[a][b][c] = 0.f;

    const float*         Ab = A + (size_t)row_base * DIN;
    const __nv_bfloat16* Bb = g_w1b + n_base;

    const uint32_t as_u = (uint32_t)__cvta_generic_to_shared(&sm.As[0][0][0]);
    const uint32_t bs_u = (uint32_t)__cvta_generic_to_shared(&sm.Bs[0][0][0]);
    const uint32_t AS_BUF = MTILE * AS_STRIDE * 2;
    const uint32_t BS_BUF = KC * BS_STRIDE * 2;

    // A staging: thread handles row tid>>2, 16-float quarter tid&3
    const int r_a = tid >> 2;
    const int q_a = tid & 3;
    float4 ar[4];

    auto ldgA = [&](int s) {
        const float* rp = Ab + (size_t)r_a * DIN + s * KC + q_a * 16;
        #pragma unroll
        for (int i = 0; i < 4; ++i)
            ar[i] = *reinterpret_cast<const float4*>(rp + i * 4);
    };
    auto stsA = [&](int buf) {
        #pragma unroll
        for (int i = 0; i < 4; ++i) {
            __nv_bfloat162 p0 = __floats2bfloat162_rn(ar[i].x, ar[i].y);
            __nv_bfloat162 p1 = __floats2bfloat162_rn(ar[i].z, ar[i].w);
            uint32_t u0 = *reinterpret_cast<uint32_t*>(&p0);
            uint32_t u1 = *reinterpret_cast<uint32_t*>(&p1);
            uint32_t dst = as_u + buf * AS_BUF
                         + (uint32_t)(r_a * AS_STRIDE + q_a * 16 + i * 4) * 2u;
            asm volatile("st.shared.v2.b32 [%0], {%1,%2};" :: "r"(dst), "r"(u0), "r"(u1));
        }
    };
    auto loadB = [&](int buf, int s) {   // KC x 256 bf16 via cp.async (4 x 16B / thread)
        const int k0 = s * KC;
        #pragma unroll
        for (int j = 0; j < 4; ++j) {
            int lin = tid + j * 512;                 // 0..2047
            int r   = lin >> 5;                      // 0..63
            int c   = lin & 31;                      // 16B chunk
            uint32_t dst = bs_u + buf * BS_BUF + (uint32_t)(r * BS_STRIDE + c * 8) * 2u;
            const void* src = Bb + (size_t)(k0 + r) * H1_ + c * 8;
            asm volatile("cp.async.cg.shared.global [%0], [%1], 16;" :: "r"(dst), "l"(src));
        }
        asm volatile("cp.async.commit_group;");
    };
    auto compute = [&](int buf) {
        const uint32_t abase = as_u + buf * AS_BUF;
        const uint32_t bbase = bs_u + buf * BS_BUF;
        const int lr = lane & 15;
        const int lc = lane >> 4;
        #pragma unroll
        for (int ks = 0; ks < KC; ks += 16) {
            uint32_t a_reg[2][4];
            #pragma unroll
            for (int mt = 0; mt < 2; ++mt) {
                uint32_t addr = abase
                    + (uint32_t)((wm * 32 + mt * 16 + lr) * AS_STRIDE + ks + lc * 8) * 2u;
                asm volatile("ldmatrix.sync.aligned.m8n8.x4.shared.b16 {%0,%1,%2,%3}, [%4];"
                             : "=r"(a_reg[mt][0]), "=r"(a_reg[mt][1]),
                               "=r"(a_reg[mt][2]), "=r"(a_reg[mt][3]) : "r"(addr));
            }
            uint32_t b_reg[8][2];
            #pragma unroll
            for (int nb = 0; nb < 4; ++nb) {   // x4.trans covers k16 x n16
                uint32_t addr = bbase
                    + (uint32_t)((ks + lr) * BS_STRIDE + wn * 64 + nb * 16 + lc * 8) * 2u;
                uint32_t r0, r1, r2, r3;
                asm volatile("ldmatrix.sync.aligned.m8n8.x4.trans.shared.b16 {%0,%1,%2,%3}, [%4];"
                             : "=r"(r0), "=r"(r1), "=r"(r2), "=r"(r3) : "r"(addr));
                b_reg[nb * 2][0] = r0;     b_reg[nb * 2][1] = r1;
                b_reg[nb * 2 + 1][0] = r2; b_reg[nb * 2 + 1][1] = r3;
            }
            #pragma unroll
            for (int mt = 0; mt < 2; ++mt)
                #pragma unroll
                for (int nt = 0; nt < 8; ++nt) {
                    asm volatile(
                        "mma.sync.aligned.m16n8k16.row.col.f32.bf16.bf16.f32 "
                        "{%0,%1,%2,%3}, {%4,%5,%6,%7}, {%8,%9}, {%0,%1,%2,%3};"
                        : "+f"(acc[mt][nt][0]), "+f"(acc[mt][nt][1]),
                          "+f"(acc[mt][nt][2]), "+f"(acc[mt][nt][3])
                        : "r"(a_reg[mt][0]), "r"(a_reg[mt][1]),
                          "r"(a_reg[mt][2]), "r"(a_reg[mt][3]),
                          "r"(b_reg[nt][0]), "r"(b_reg[nt][1]));
                }
        }
    };

    // ---- prologue: stage 0 resident before first compute ----
    ldgA(0);
    loadB(0, 0);
    stsA(0);
    asm volatile("cp.async.wait_group 0;");
    __syncthreads();

    // ---- pipelined main loop: next-stage loads issued BEFORE compute ----
    for (int s = 0; s < NSTG; ++s) {
        const int buf = s & 1;
        if (s + 1 < NSTG) {
            ldgA(s + 1);            // DRAM latency hidden behind compute(s)
            loadB(buf ^ 1, s + 1);  // safe: all warps synced past compute(s-1)
        }
        compute(buf);
        if (s + 1 < NSTG) stsA(buf ^ 1);
        asm volatile("cp.async.wait_group 0;");   // only B(s+1) outstanding here
        __syncthreads();
    }

    // ---- epilogue: bias + relu + weff-dot, reduce to per-row z ----
    const int g = lane >> 2, tig = lane & 3;
    #pragma unroll
    for (int mt = 0; mt < 2; ++mt) {
        float sa = 0.f, sb = 0.f;
        #pragma unroll
        for (int nt = 0; nt < 8; ++nt) {
            int c0 = wn * 64 + nt * 8 + tig * 2;
            float w0 = sm.wsm[c0],  w1 = sm.wsm[c0 + 1];
            float q0 = sm.b1s[c0],  q1 = sm.b1s[c0 + 1];
            float h0 = fmaxf(acc[mt][nt][0] + q0, 0.f);
            float h1 = fmaxf(acc[mt][nt][1] + q1, 0.f);
            float h2 = fmaxf(acc[mt][nt][2] + q0, 0.f);
            float h3 = fmaxf(acc[mt][nt][3] + q1, 0.f);
            sa += h0 * w0 + h1 * w1;
            sb += h2 * w0 + h3 * w1;
        }
        sa += __shfl_xor_sync(0xffffffffu, sa, 1);
        sa += __shfl_xor_sync(0xffffffffu, sa, 2);
        sb += __shfl_xor_sync(0xffffffffu, sb, 1);
        sb += __shfl_xor_sync(0xffffffffu, sb, 2);
        if (tig == 0) {
            atomicAdd(&sm.zs[wm * 32 + mt * 16 + g], sa);
            atomicAdd(&sm.zs[wm * 32 + mt * 16 + g + 8], sb);
        }
    }
    __syncthreads();
    if (tid < MTILE) {
        if (nt_blk == 0) g_z[row_base + tid] = sm.zs[tid];
        else atomicAdd(&g_z[row_base + tid], sm.zs[tid]);
    }
}

// NOTE on g_z: the two N-halves of each row land in different CTAs; half 0
// plain-stores, half 1 atomicAdd-accumulates. Ordering hazard! Fix: make it
// deterministic with a partials buffer instead.
__device__ float g_zpart[2][ROWS];

__global__ __launch_bounds__(256, 2)
void zmerge_kernel() { /* unused - see below */ }

// ---------------- kernel 2: per-sample sigmoid + ragged top-k mean ----------------
__global__ void topk_kernel(const int* __restrict__ seq_len, float* __restrict__ out) {
    __shared__ float s[T_];
    __shared__ float red[8];
    const int b   = blockIdx.x;
    const int tid = threadIdx.x;
    const int L   = seq_len[b];
    const float beff = g_beff;

    for (int i = tid; i < T_; i += blockDim.x) {
        float v = -1.0f;  // below sigmoid range -> never in top-k
        if (i < L) {
            float z = g_zpart[0][b * T_ + i] + g_zpart[1][b * T_ + i] + beff;
            v = 1.0f / (1.0f + expf(-z));
        }
        s[i] = v;
    }
    __syncthreads();

    // bitonic sort, descending
    for (int size = 2; size <= T_; size <<= 1) {
        for (int stride = size >> 1; stride > 0; stride >>= 1) {
            for (int i = tid; i < T_; i += blockDim.x) {
                int j = i ^ stride;
                if (j > i) {
                    bool desc = ((i & size) == 0);
                    float x = s[i], y = s[j];
                    if ((x < y) == desc) { s[i] = y; s[j] = x; }
                }
            }
            __syncthreads();
        }
    }

    const int k = L / 16 + 1;   // k <= L always
    float p = 0.f;
    for (int i = tid; i < k; i += blockDim.x) p += s[i];
    p += __shfl_xor_sync(0xffffffffu, p, 16);
    p += __shfl_xor_sync(0xffffffffu, p, 8);
    p += __shfl_xor_sync(0xffffffffu, p, 4);
    p += __shfl_xor_sync(0xffffffffu, p, 2);
    p += __shfl_xor_sync(0xffffffffu, p, 1);
    if ((tid & 31) == 0) red[tid >> 5] = p;
    __syncthreads();
    if (tid == 0) {
        float sum = 0.f;
        #pragma unroll
        for (int w = 0; w < 8; ++w) sum += red[w];
        out[b] = sum / (float)k;
    }
}

// Patch the GEMM epilogue target to the deterministic partials buffer:
// (g_z kept for ABI stability of the file but unused)
__global__ __launch_bounds__(512, 1)
void dummy_unused() {}

// Redefine: the GEMM kernel above writes g_z with a store/atomic race between
// the two N-half CTAs of the same row. To keep determinism we instead route
// through g_zpart: replace the final write. Since CUDA C can't patch the
// kernel post-hoc, the actual fix is in the kernel body — see sm.zs store:
// we write to g_zpart[nt_blk] there. (g_z left unused.)

// ---------------- entry point ----------------
// Inputs: 0 avf_out [32,2048,1024] f32; 1 W1 [1024,512]; 2 b1 [512]; 3 W2 [512,32];
//         4 b2 [32]; 5 W3 [32,1]; 6 b3 [1]; 7 seq_len [32] i32. Output: [32] f32.
extern "C" void kernel_launch(void* const* d_in, const int* in_sizes, int n_in,
                              void* d_out, int out_size);

// ---- final GEMM kernel with deterministic partial writes (used by launch) ----
__global__ __launch_bounds__(512, 1)
void mlp_gemm_kernel2(const float* __restrict__ A, const float* __restrict__ b1) {
    extern __shared__ char smem_raw[];
    Smem& sm = *reinterpret_cast<Smem*>(smem_raw);

    const int tid  = threadIdx.x;
    const int lane = tid & 31;
    const int warp = tid >> 5;
    const int wm   = warp >> 2;
    const int wn   = warp & 3;

    const int nt_blk   = blockIdx.x & 1;
    const int row_tile = blockIdx.x >> 1;
    const int row_base = row_tile * MTILE;
    const int n_base   = nt_blk * NTILE;

    if (tid < NTILE) {
        sm.b1s[tid] = b1[n_base + tid];
        sm.wsm[tid] = g_weff[n_base + tid];
    }
    if (tid < MTILE) sm.zs[tid] = 0.f;

    float acc[2][8][4];
    #pragma unroll
    for (int a = 0; a < 2; ++a)
        #pragma unroll
        for (int b = 0; b < 8; ++b)
            #pragma unroll
            for (int c = 0; c < 4; ++c) acc[a][b][c] = 0.f;

    const float*         Ab = A + (size_t)row_base * DIN;
    const __nv_bfloat16* Bb = g_w1b + n_base;

    const uint32_t as_u = (uint32_t)__cvta_generic_to_shared(&sm.As[0][0][0]);
    const uint32_t bs_u = (uint32_t)__cvta_generic_to_shared(&sm.Bs[0][0][0]);
    const uint32_t AS_BUF = MTILE * AS_STRIDE * 2;
    const uint32_t BS_BUF = KC * BS_STRIDE * 2;

    const int r_a = tid >> 2;
    const int q_a = tid & 3;
    float4 ar[4];

    auto ldgA = [&](int s) {
        const float* rp = Ab + (size_t)r_a * DIN + s * KC + q_a * 16;
        #pragma unroll
        for (int i = 0; i < 4; ++i)
            ar[i] = *reinterpret_cast<const float4*>(rp + i * 4);
    };
    auto stsA = [&](int buf) {
        #pragma unroll
        for (int i = 0; i < 4; ++i) {
            __nv_bfloat162 p0 = __floats2bfloat162_rn(ar[i].x, ar[i].y);
            __nv_bfloat162 p1 = __floats2bfloat162_rn(ar[i].z, ar[i].w);
            uint32_t u0 = *reinterpret_cast<uint32_t*>(&p0);
            uint32_t u1 = *reinterpret_cast<uint32_t*>(&p1);
            uint32_t dst = as_u + buf * AS_BUF
                         + (uint32_t)(r_a * AS_STRIDE + q_a * 16 + i * 4) * 2u;
            asm volatile("st.shared.v2.b32 [%0], {%1,%2};" :: "r"(dst), "r"(u0), "r"(u1));
        }
    };
    auto loadB = [&](int buf, int s) {
        const int k0 = s * KC;
        #pragma unroll
        for (int j = 0; j < 4; ++j) {
            int lin = tid + j * 512;
            int r   = lin >> 5;
            int c   = lin & 31;
            uint32_t dst = bs_u + buf * BS_BUF + (uint32_t)(r * BS_STRIDE + c * 8) * 2u;
            const void* src = Bb + (size_t)(k0 + r) * H1_ + c * 8;
            asm volatile("cp.async.cg.shared.global [%0], [%1], 16;" :: "r"(dst), "l"(src));
        }
        asm volatile("cp.async.commit_group;");
    };
    auto compute = [&](int buf) {
        const uint32_t abase = as_u + buf * AS_BUF;
        const uint32_t bbase = bs_u + buf * BS_BUF;
        const int lr = lane & 15;
        const int lc = lane >> 4;
        #pragma unroll
        for (int ks = 0; ks < KC; ks += 16) {
            uint32_t a_reg[2][4];
            #pragma unroll
            for (int mt = 0; mt < 2; ++mt) {
                uint32_t addr = abase
                    + (uint32_t)((wm * 32 + mt * 16 + lr) * AS_STRIDE + ks + lc * 8) * 2u;
                asm volatile("ldmatrix.sync.aligned.m8n8.x4.shared.b16 {%0,%1,%2,%3}, [%4];"
                             : "=r"(a_reg[mt][0]), "=r"(a_reg[mt][1]),
                               "=r"(a_reg[mt][2]), "=r"(a_reg[mt][3]) : "r"(addr));
            }
            uint32_t b_reg[8][2];
            #pragma unroll
            for (int nb = 0; nb < 4; ++nb) {
                uint32_t addr = bbase
                    + (uint32_t)((ks + lr) * BS_STRIDE + wn * 64 + nb * 16 + lc * 8) * 2u;
                uint32_t r0, r1, r2, r3;
                asm volatile("ldmatrix.sync.aligned.m8n8.x4.trans.shared.b16 {%0,%1,%2,%3}, [%4];"
                             : "=r"(r0), "=r"(r1), "=r"(r2), "=r"(r3) : "r"(addr));
                b_reg[nb * 2][0] = r0;     b_reg[nb * 2][1] = r1;
                b_reg[nb * 2 + 1][0] = r2; b_reg[nb * 2 + 1][1] = r3;
            }
            #pragma unroll
            for (int mt = 0; mt < 2; ++mt)
                #pragma unroll
                for (int nt = 0; nt < 8; ++nt) {
                    asm volatile(
                        "mma.sync.aligned.m16n8k16.row.col.f32.bf16.bf16.f32 "
                        "{%0,%1,%2,%3}, {%4,%5,%6,%7}, {%8,%9}, {%0,%1,%2,%3};"
                        : "+f"(acc[mt][nt][0]), "+f"(acc[mt][nt][1]),
                          "+f"(acc[mt][nt][2]), "+f"(acc[mt][nt][3])
                        : "r"(a_reg[mt][0]), "r"(a_reg[mt][1]),
                          "r"(a_reg[mt][2]), "r"(a_reg[mt][3]),
                          "r"(b_reg[nt][0]), "r"(b_reg[nt][1]));
                }
        }
    };

    ldgA(0);
    loadB(0, 0);
    stsA(0);
    asm volatile("cp.async.wait_group 0;");
    __syncthreads();

    for (int s = 0; s < NSTG; ++s) {
        const int buf = s & 1;
        if (s + 1 < NSTG) {
            ldgA(s + 1);
            loadB(buf ^ 1, s + 1);
        }
        compute(buf);
        if (s + 1 < NSTG) stsA(buf ^ 1);
        asm volatile("cp.async.wait_group 0;");
        __syncthreads();
    }

    const int g = lane >> 2, tig = lane & 3;
    #pragma unroll
    for (int mt = 0; mt < 2; ++mt) {
        float sa = 0.f, sb = 0.f;
        #pragma unroll
        for (int nt = 0; nt < 8; ++nt) {
            int c0 = wn * 64 + nt * 8 + tig * 2;
            float w0 = sm.wsm[c0],  w1 = sm.wsm[c0 + 1];
            float q0 = sm.b1s[c0],  q1 = sm.b1s[c0 + 1];
            float h0 = fmaxf(acc[mt][nt][0] + q0, 0.f);
            float h1 = fmaxf(acc[mt][nt][1] + q1, 0.f);
            float h2 = fmaxf(acc[mt][nt][2] + q0, 0.f);
            float h3 = fmaxf(acc[mt][nt][3] + q1, 0.f);
            sa += h0 * w0 + h1 * w1;
            sb += h2 * w0 + h3 * w1;
        }
        sa += __shfl_xor_sync(0xffffffffu, sa, 1);
        sa += __shfl_xor_sync(0xffffffffu, sa, 2);
        sb += __shfl_xor_sync(0xffffffffu, sb, 1);
        sb += __shfl_xor_sync(0xffffffffu, sb, 2);
        if (tig == 0) {
            atomicAdd(&sm.zs[wm * 32 + mt * 16 + g], sa);
            atomicAdd(&sm.zs[wm * 32 + mt * 16 + g + 8], sb);
        }
    }
    __syncthreads();
    if (tid < MTILE)
        g_zpart[nt_blk][row_base + tid] = sm.zs[tid];
}

extern "C" void kernel_launch(void* const* d_in, const int* in_sizes, int n_in,
                              void* d_out, int out_size) {
    const float* avf = (const float*)d_in[0];
    const float* W1  = (const float*)d_in[1];
    const float* b1  = (const float*)d_in[2];
    const float* W2  = (const float*)d_in[3];
    const float* b2  = (const float*)d_in[4];
    const float* W3  = (const float*)d_in[5];
    const float* b3  = (const float*)d_in[6];
    const int*   seq = (const int*)d_in[7];
    float*       out = (float*)d_out;

    cudaFuncSetAttribute(mlp_gemm_kernel2,
                         cudaFuncAttributeMaxDynamicSharedMemorySize,
                         (int)sizeof(Smem));

    prep_kernel<<<2048, 256>>>(W1, W2, b2, W3, b3);
    mlp_gemm_kernel2<<<(ROWS / MTILE) * (H1_ / NTILE), 512, sizeof(Smem)>>>(avf, b1);
    topk_kernel<<<NB_, 256>>>(seq, out);
}